// round 9
// baseline (speedup 1.0000x reference)
#include <cuda_runtime.h>
#include <cuda_fp16.h>

#define NN 50000
#define EE 800000
#define D  128

// ---------------- scratch (static device globals: allowed) ----------------
__device__ __half g_h [(size_t)NN * D];    // pre-scaled messages h' = dinv*(x@W), fp16
__device__ float g_agg1[(size_t)NN * D];   // layer-1 aggregation output (fp32)
__device__ float g_agg2[(size_t)NN * D];   // layer-2 aggregation output (fp32)
__device__ float g_dinv[NN];
__device__ int   g_cnt [NN];               // degree histogram / fill counters
__device__ int   g_rowptr[NN + 1];
__device__ int   g_srcs[EE];               // src ids bucketed by dst
__device__ int   g_tmp [NN];               // intra-block inclusive scan values
__device__ int   g_bsum[64];               // per-block totals
__device__ float g_sum  [2][D];
__device__ float g_sumsq[2][D];
__device__ int   g_is64;                   // 1 if edge_index is really int64

// ---------------- f32x2 packed-FMA helpers (sm_103a) ----------------
#define FMA2(d, a, b, c) \
    asm("fma.rn.f32x2 %0, %1, %2, %3;" : "=l"(d) : "l"(a), "l"(b), "l"(c))
#define PACK2(d, lo, hi) \
    asm("mov.b64 %0, {%1, %2};" : "=l"(d) : "f"(lo), "f"(hi))
#define UNPACK2(lo, hi, v) \
    asm("mov.b64 {%0, %1}, %2;" : "=f"(lo), "=f"(hi) : "l"(v))

__device__ __forceinline__ int edge_at(const void* ei, long long idx, int is64) {
    if (is64) return (int)((const long long*)ei)[idx];
    return ((const int*)ei)[idx];
}

// ---------------- init: zero counters/stats + dtype probe (block 0) ----------------
__global__ void init_zero_detect(const int* __restrict__ words, int nwords, int n) {
    int i = blockIdx.x * blockDim.x + threadIdx.x;
    if (i < n) g_cnt[i] = 0;
    if (i < D) {
        g_sum[0][i] = 0.f; g_sumsq[0][i] = 0.f;
        g_sum[1][i] = 0.f; g_sumsq[1][i] = 0.f;
    }
    if (blockIdx.x == 0) {
        __shared__ int s_nz;
        int t = threadIdx.x;
        if (t == 0) s_nz = 0;
        __syncthreads();
        int nz = 0;
        for (int w = 2 * t + 1; w < nwords; w += 2 * blockDim.x)
            nz |= (words[w] != 0);
        if (nz) atomicOr(&s_nz, 1);
        __syncthreads();
        if (t == 0) g_is64 = s_nz ? 0 : 1;
    }
}

// ---------------- CSR build ----------------
__global__ void count_deg(const void* __restrict__ ei, int ne, int n) {
    int e = blockIdx.x * blockDim.x + threadIdx.x;
    if (e >= ne) return;
    int is64 = g_is64;
    int d = edge_at(ei, (long long)ne + e, is64);       // dst
    if ((unsigned)d < (unsigned)n) atomicAdd(&g_cnt[d], 1);
}

__global__ void scan_phase1(int n) {            // grid = ceil(n/1024), 1024 thr
    __shared__ int sh[1024];
    int t = threadIdx.x;
    int i = blockIdx.x * 1024 + t;
    int v = (i < n) ? g_cnt[i] : 0;
    sh[t] = v;
    __syncthreads();
#pragma unroll
    for (int off = 1; off < 1024; off <<= 1) {
        int u = (t >= off) ? sh[t - off] : 0;
        __syncthreads();
        sh[t] += u;
        __syncthreads();
    }
    if (i < n) g_tmp[i] = sh[t];                // inclusive within block
    if (t == 1023) g_bsum[blockIdx.x] = sh[1023];
}

// phase3 with embedded block-sum scan (phase2 done redundantly per block)
__global__ void scan_phase3(int n, int nblk) {  // 1024 thr
    __shared__ int sbs[64];
    int t = threadIdx.x;
    if (t < 64) sbs[t] = (t < nblk) ? g_bsum[t] : 0;
    __syncthreads();
#pragma unroll
    for (int off = 1; off < 64; off <<= 1) {
        int v = (t < 64 && t >= off) ? sbs[t - off] : 0;
        __syncthreads();
        if (t < 64) sbs[t] += v;
        __syncthreads();
    }
    int i = blockIdx.x * blockDim.x + t;
    if (i > n) return;
    if (i == n) { g_rowptr[n] = sbs[nblk - 1]; return; }
    int blk = i >> 10;
    int c = g_cnt[i];
    int excl = g_tmp[i] - c + (blk ? sbs[blk - 1] : 0);
    g_rowptr[i] = excl;
    g_dinv[i] = rsqrtf((float)(c + 1));         // +1 self-loop
    g_cnt[i] = 0;
}

__global__ void fill_buckets(const void* __restrict__ ei, int ne, int n) {
    int e = blockIdx.x * blockDim.x + threadIdx.x;
    if (e >= ne) return;
    int is64 = g_is64;
    int s = edge_at(ei, e, is64);                        // src
    int d = edge_at(ei, (long long)ne + e, is64);        // dst
    if ((unsigned)d < (unsigned)n && (unsigned)s < (unsigned)n) {
        int p = g_rowptr[d] + atomicAdd(&g_cnt[d], 1);
        g_srcs[p] = s;
    }
}

// ---------------- GEMM: g_h = fp16( dinv[r] * (X @ W) ) -----------------------
// LAYER==1: input = g_agg1 with BN+PReLU fused on load; BN finalize computed
// per-block in smem from g_sum[0]/g_sumsq[0] (replaces bn_finalize kernel).
// X tile stored DUPLICATED as float2 so the f32x2 'a' operand is one LDS.64
// (no PACK movs in the inner loop).
template<int LAYER>
__global__ void __launch_bounds__(256, 2)
gemm_kernel(const float* __restrict__ Xext, const float* __restrict__ W,
            const float* __restrict__ gbn, const float* __restrict__ bebn,
            const float* __restrict__ alpha, float inv_n, int n)
{
    __shared__ float2 Xs2[16][132];  // duplicated pairs; padded rows
    __shared__ float  Ws[16][128];
    __shared__ float  s_sc[128], s_sh[128];

    const float* __restrict__ X = (LAYER == 0) ? Xext : g_agg1;

    int tid  = threadIdx.x;
    int row0 = blockIdx.x * 128;
    int tx = tid & 15, ty = tid >> 4;
    float al = (LAYER == 1) ? __ldg(alpha) : 0.f;

    if (LAYER == 1) {                 // per-block BN finalize (cheap, deterministic)
        if (tid < 128) {
            float mu  = g_sum[0][tid] * inv_n;
            float var = g_sumsq[0][tid] * inv_n - mu * mu;
            float rs  = rsqrtf(var + 1e-5f);
            float scl = gbn[tid] * rs;
            s_sc[tid] = scl;
            s_sh[tid] = bebn[tid] - mu * scl;
        }
        __syncthreads();
    }

    unsigned long long acc2[8][4];              // 8 rows x 4 packed col-pairs
    {
        unsigned long long z; PACK2(z, 0.f, 0.f);
#pragma unroll
        for (int i = 0; i < 8; i++)
#pragma unroll
            for (int j = 0; j < 4; j++) acc2[i][j] = z;
    }

    for (int k0 = 0; k0 < D; k0 += 16) {
#pragma unroll
        for (int l = 0; l < 2; l++) {
            int idx = tid + l * 256;            // 512 float4 slots = 128x16 tile
            int r = idx >> 2, c4 = idx & 3;
            int gr = row0 + r;
            float4 v = make_float4(0.f, 0.f, 0.f, 0.f);
            if (gr < n) v = *(const float4*)(X + (size_t)gr * D + k0 + c4 * 4);
            if (LAYER == 1) {
                int c = k0 + c4 * 4;
                float4 s4 = *(const float4*)&s_sc[c];
                float4 h4 = *(const float4*)&s_sh[c];
                v.x = fmaf(s4.x, v.x, h4.x); v.x = v.x > 0.f ? v.x : al * v.x;
                v.y = fmaf(s4.y, v.y, h4.y); v.y = v.y > 0.f ? v.y : al * v.y;
                v.z = fmaf(s4.z, v.z, h4.z); v.z = v.z > 0.f ? v.z : al * v.z;
                v.w = fmaf(s4.w, v.w, h4.w); v.w = v.w > 0.f ? v.w : al * v.w;
            }
            Xs2[c4 * 4 + 0][r] = make_float2(v.x, v.x);
            Xs2[c4 * 4 + 1][r] = make_float2(v.y, v.y);
            Xs2[c4 * 4 + 2][r] = make_float2(v.z, v.z);
            Xs2[c4 * 4 + 3][r] = make_float2(v.w, v.w);
        }
#pragma unroll
        for (int l = 0; l < 2; l++) {
            int idx = tid + l * 256;
            int r = idx >> 5, c4 = idx & 31;
            *(float4*)&Ws[r][c4 * 4] = *(const float4*)(W + (size_t)(k0 + r) * D + c4 * 4);
        }
        __syncthreads();

#pragma unroll
        for (int kk = 0; kk < 16; kk++) {
            unsigned long long a2[8], b2[4];
#pragma unroll
            for (int i = 0; i < 8; i++)
                a2[i] = *(const unsigned long long*)&Xs2[kk][ty * 8 + i];
#pragma unroll
            for (int j = 0; j < 4; j++)
                b2[j] = *(const unsigned long long*)&Ws[kk][tx * 8 + j * 2];
#pragma unroll
            for (int i = 0; i < 8; i++)
#pragma unroll
                for (int j = 0; j < 4; j++)
                    FMA2(acc2[i][j], a2[i], b2[j], acc2[i][j]);
        }
        __syncthreads();
    }

    // epilogue: scale by dinv, convert to fp16, one 16B store of 8 halves per row
#pragma unroll
    for (int i = 0; i < 8; i++) {
        int r = row0 + ty * 8 + i;
        if (r < n) {
            float dv = g_dinv[r];
            float e[8];
#pragma unroll
            for (int j = 0; j < 4; j++) {
                float lo, hi;
                UNPACK2(lo, hi, acc2[i][j]);
                e[j * 2 + 0] = lo * dv;
                e[j * 2 + 1] = hi * dv;
            }
            __half2 p[4];
#pragma unroll
            for (int j = 0; j < 4; j++)
                p[j] = __floats2half2_rn(e[j * 2], e[j * 2 + 1]);
            *(uint4*)(g_h + (size_t)r * D + tx * 8) = *(uint4*)p;
        }
    }
}

// ---------------- CSR gather: warp per (node, half-row), deep-MLP + idx prefetch ----
template<int LAYER>
__global__ void __launch_bounds__(256)
gather_agg(const float* __restrict__ bias, int n)
{
    int lane = threadIdx.x & 31;
    int warp = (int)((blockIdx.x * blockDim.x + threadIdx.x) >> 5);
    int nwarps = (int)((gridDim.x * blockDim.x) >> 5);
    float* __restrict__ A = (LAYER == 0) ? g_agg1 : g_agg2;
    float* __restrict__ S = g_sum[LAYER];
    float* __restrict__ Q = g_sumsq[LAYER];

    int nitems = 2 * n;
    float2 ss = make_float2(0.f, 0.f);
    float2 qq = make_float2(0.f, 0.f);
    int last_c = 0;

    for (int item = warp; item < nitems; item += nwarps) {
        int node = item >> 1;
        int c = ((item & 1) << 6) + lane * 2;       // column pair
        last_c = c;
        int beg = g_rowptr[node], end = g_rowptr[node + 1];
        const __half* __restrict__ H = g_h + c;

        // self-loop
        float2 acc = __half22float2(*(const __half2*)(H + (size_t)node * D));

        int e = beg;
        // prefetch first index group
        int sv = (e + 8 <= end) ? g_srcs[e + (lane & 7)] : 0;
        while (e + 8 <= end) {
            int sv_cur = sv;
            int en = e + 8;
            if (en + 8 <= end) sv = g_srcs[en + (lane & 7)];   // prefetch next
            int s0 = __shfl_sync(0xffffffffu, sv_cur, 0);
            int s1 = __shfl_sync(0xffffffffu, sv_cur, 1);
            int s2 = __shfl_sync(0xffffffffu, sv_cur, 2);
            int s3 = __shfl_sync(0xffffffffu, sv_cur, 3);
            int s4 = __shfl_sync(0xffffffffu, sv_cur, 4);
            int s5 = __shfl_sync(0xffffffffu, sv_cur, 5);
            int s6 = __shfl_sync(0xffffffffu, sv_cur, 6);
            int s7 = __shfl_sync(0xffffffffu, sv_cur, 7);
            __half2 u0 = *(const __half2*)(H + (size_t)s0 * D);
            __half2 u1 = *(const __half2*)(H + (size_t)s1 * D);
            __half2 u2 = *(const __half2*)(H + (size_t)s2 * D);
            __half2 u3 = *(const __half2*)(H + (size_t)s3 * D);
            __half2 u4 = *(const __half2*)(H + (size_t)s4 * D);
            __half2 u5 = *(const __half2*)(H + (size_t)s5 * D);
            __half2 u6 = *(const __half2*)(H + (size_t)s6 * D);
            __half2 u7 = *(const __half2*)(H + (size_t)s7 * D);
            float2 f0 = __half22float2(u0), f1 = __half22float2(u1);
            float2 f2 = __half22float2(u2), f3 = __half22float2(u3);
            float2 f4 = __half22float2(u4), f5 = __half22float2(u5);
            float2 f6 = __half22float2(u6), f7 = __half22float2(u7);
            acc.x += ((f0.x + f1.x) + (f2.x + f3.x)) + ((f4.x + f5.x) + (f6.x + f7.x));
            acc.y += ((f0.y + f1.y) + (f2.y + f3.y)) + ((f4.y + f5.y) + (f6.y + f7.y));
            e = en;
        }
        for (; e < end; e++) {
            int s = g_srcs[e];
            float2 f = __half22float2(*(const __half2*)(H + (size_t)s * D));
            acc.x += f.x; acc.y += f.y;
        }
        float dv = g_dinv[node];
        float bx = bias[c], by = bias[c + 1];
        float ox = fmaf(dv, acc.x, bx);
        float oy = fmaf(dv, acc.y, by);
        *(float2*)(A + (size_t)node * D + c) = make_float2(ox, oy);
        ss.x += ox; ss.y += oy;
        qq.x = fmaf(ox, ox, qq.x); qq.y = fmaf(oy, oy, qq.y);
    }
    atomicAdd(S + last_c + 0, ss.x); atomicAdd(S + last_c + 1, ss.y);
    atomicAdd(Q + last_c + 0, qq.x); atomicAdd(Q + last_c + 1, qq.y);
}

// ---------------- final apply (BN finalize folded in per-block) ----------------
__global__ void apply_out(const float* __restrict__ g, const float* __restrict__ be,
                          const float* __restrict__ alpha, float inv_n,
                          float* __restrict__ out, int n)
{
    __shared__ float s_sc[128], s_sh[128];
    int t = threadIdx.x;
    if (t < 128) {
        float mu  = g_sum[1][t] * inv_n;
        float var = g_sumsq[1][t] * inv_n - mu * mu;
        float rs  = rsqrtf(var + 1e-5f);
        float scl = g[t] * rs;
        s_sc[t] = scl;
        s_sh[t] = be[t] - mu * scl;
    }
    __syncthreads();

    int i = blockIdx.x * blockDim.x + t;        // one float4 each
    if (i >= n * 32) return;
    int c = (i & 31) * 4;
    float al = __ldg(alpha);
    float4 v  = *(const float4*)(g_agg2 + (size_t)i * 4);
    float4 s4 = *(const float4*)&s_sc[c];
    float4 h4 = *(const float4*)&s_sh[c];
    v.x = fmaf(s4.x, v.x, h4.x); v.x = v.x > 0.f ? v.x : al * v.x;
    v.y = fmaf(s4.y, v.y, h4.y); v.y = v.y > 0.f ? v.y : al * v.y;
    v.z = fmaf(s4.z, v.z, h4.z); v.z = v.z > 0.f ? v.z : al * v.z;
    v.w = fmaf(s4.w, v.w, h4.w); v.w = v.w > 0.f ? v.w : al * v.w;
    *(float4*)(out + (size_t)i * 4) = v;
}

// ---------------- launch ----------------
extern "C" void kernel_launch(void* const* d_in, const int* in_sizes, int n_in,
                              void* d_out, int out_size)
{
    const float* x   = (const float*)d_in[0];
    const void*  ei  = d_in[1];
    const float* W1  = (const float*)d_in[2];
    const float* b1  = (const float*)d_in[3];
    const float* g1  = (const float*)d_in[4];
    const float* be1 = (const float*)d_in[5];
    const float* a1  = (const float*)d_in[6];
    const float* W2  = (const float*)d_in[7];
    const float* b2  = (const float*)d_in[8];
    const float* g2  = (const float*)d_in[9];
    const float* be2 = (const float*)d_in[10];
    const float* a2  = (const float*)d_in[11];

    int ne = in_sizes[1] / 2;        // 2*E elements either way
    int n  = in_sizes[0] / D;
    float inv_n = 1.f / (float)n;

    int nb256  = (n + 255) / 256;
    int eb256  = (ne + 255) / 256;
    int gemm_b = (n + 127) / 128;
    int gat_b  = 1184;               // ~full residency: 148 SMs x 8 blocks
    int out_b  = (n * 32 + 255) / 256;
    int probe_words = (2 * ne < 4096) ? 2 * ne : 4096;
    int nblk1024 = (n + 1023) / 1024;

    init_zero_detect<<<nb256, 256>>>((const int*)ei, probe_words, n);   // 1
    count_deg  <<<eb256, 256>>>(ei, ne, n);                             // 2
    scan_phase1<<<nblk1024, 1024>>>(n);                                 // 3
    scan_phase3<<<(n + 1024) / 1024, 1024>>>(n, nblk1024);              // 4
    fill_buckets<<<eb256, 256>>>(ei, ne, n);                            // 5

    // ---- layer 1 ----  (launch #6 = gemm<0> lands in the ncu -s 5 window)
    gemm_kernel<0><<<gemm_b, 256>>>(x, W1, nullptr, nullptr, a1, 0.f, n);
    gather_agg<0> <<<gat_b, 256>>>(b1, n);                              // 7

    // ---- layer 2 (BN+PReLU of layer 1 fused into GEMM load) ----
    gemm_kernel<1><<<gemm_b, 256>>>(nullptr, W2, g1, be1, a1, inv_n, n);// 8
    gather_agg<1> <<<gat_b, 256>>>(b2, n);                              // 9

    apply_out<<<out_b, 256>>>(g2, be2, a2, inv_n, (float*)d_out, n);    // 10
}

// round 10
// speedup vs baseline: 1.0827x; 1.0827x over previous
#include <cuda_runtime.h>
#include <cuda_fp16.h>

#define NN 50000
#define EE 800000
#define D  128

// ---------------- scratch (static device globals: allowed) ----------------
__device__ __half g_h [(size_t)NN * D];    // pre-scaled messages h' = dinv*(x@W), fp16
__device__ float g_agg1[(size_t)NN * D];   // layer-1 aggregation output (fp32)
__device__ float g_agg2[(size_t)NN * D];   // layer-2 aggregation output (fp32)
__device__ float g_dinv[NN];
__device__ int   g_cnt [NN];               // degree histogram / fill counters
__device__ int   g_rowptr[NN + 1];
__device__ int   g_srcs[EE];               // src ids bucketed by dst
__device__ int   g_tmp [NN];               // intra-block inclusive scan values
__device__ int   g_bsum[64];               // per-block totals
__device__ float g_sum  [2][D];
__device__ float g_sumsq[2][D];
__device__ int   g_is64;                   // 1 if edge_index is really int64

// ---------------- f32x2 packed-FMA helpers (sm_103a) ----------------
#define FMA2(d, a, b, c) \
    asm("fma.rn.f32x2 %0, %1, %2, %3;" : "=l"(d) : "l"(a), "l"(b), "l"(c))
#define PACK2(d, lo, hi) \
    asm("mov.b64 %0, {%1, %2};" : "=l"(d) : "f"(lo), "f"(hi))
#define UNPACK2(lo, hi, v) \
    asm("mov.b64 {%0, %1}, %2;" : "=f"(lo), "=f"(hi) : "l"(v))

__device__ __forceinline__ int edge_at(const void* ei, long long idx, int is64) {
    if (is64) return (int)((const long long*)ei)[idx];
    return ((const int*)ei)[idx];
}

// ---------------- init: zero counters/stats + dtype probe (block 0) ----------------
__global__ void init_zero_detect(const int* __restrict__ words, int nwords, int n) {
    int i = blockIdx.x * blockDim.x + threadIdx.x;
    if (i < n) g_cnt[i] = 0;
    if (i < D) {
        g_sum[0][i] = 0.f; g_sumsq[0][i] = 0.f;
        g_sum[1][i] = 0.f; g_sumsq[1][i] = 0.f;
    }
    if (blockIdx.x == 0) {
        __shared__ int s_nz;
        int t = threadIdx.x;
        if (t == 0) s_nz = 0;
        __syncthreads();
        int nz = 0;
        for (int w = 2 * t + 1; w < nwords; w += 2 * blockDim.x)
            nz |= (words[w] != 0);
        if (nz) atomicOr(&s_nz, 1);
        __syncthreads();
        if (t == 0) g_is64 = s_nz ? 0 : 1;
    }
}

// ---------------- CSR build ----------------
__global__ void count_deg(const void* __restrict__ ei, int ne, int n) {
    int e = blockIdx.x * blockDim.x + threadIdx.x;
    if (e >= ne) return;
    int is64 = g_is64;
    int d = edge_at(ei, (long long)ne + e, is64);       // dst
    if ((unsigned)d < (unsigned)n) atomicAdd(&g_cnt[d], 1);
}

__global__ void scan_phase1(int n) {            // grid = ceil(n/1024), 1024 thr
    __shared__ int sh[1024];
    int t = threadIdx.x;
    int i = blockIdx.x * 1024 + t;
    int v = (i < n) ? g_cnt[i] : 0;
    sh[t] = v;
    __syncthreads();
#pragma unroll
    for (int off = 1; off < 1024; off <<= 1) {
        int u = (t >= off) ? sh[t - off] : 0;
        __syncthreads();
        sh[t] += u;
        __syncthreads();
    }
    if (i < n) g_tmp[i] = sh[t];                // inclusive within block
    if (t == 1023) g_bsum[blockIdx.x] = sh[1023];
}

// phase3 with embedded block-sum scan (phase2 done redundantly per block)
__global__ void scan_phase3(int n, int nblk) {  // 1024 thr
    __shared__ int sbs[64];
    int t = threadIdx.x;
    if (t < 64) sbs[t] = (t < nblk) ? g_bsum[t] : 0;
    __syncthreads();
#pragma unroll
    for (int off = 1; off < 64; off <<= 1) {
        int v = (t < 64 && t >= off) ? sbs[t - off] : 0;
        __syncthreads();
        if (t < 64) sbs[t] += v;
        __syncthreads();
    }
    int i = blockIdx.x * blockDim.x + t;
    if (i > n) return;
    if (i == n) { g_rowptr[n] = sbs[nblk - 1]; return; }
    int blk = i >> 10;
    int c = g_cnt[i];
    int excl = g_tmp[i] - c + (blk ? sbs[blk - 1] : 0);
    g_rowptr[i] = excl;
    g_dinv[i] = rsqrtf((float)(c + 1));         // +1 self-loop
    g_cnt[i] = 0;
}

__global__ void fill_buckets(const void* __restrict__ ei, int ne, int n) {
    int e = blockIdx.x * blockDim.x + threadIdx.x;
    if (e >= ne) return;
    int is64 = g_is64;
    int s = edge_at(ei, e, is64);                        // src
    int d = edge_at(ei, (long long)ne + e, is64);        // dst
    if ((unsigned)d < (unsigned)n && (unsigned)s < (unsigned)n) {
        int p = g_rowptr[d] + atomicAdd(&g_cnt[d], 1);
        g_srcs[p] = s;
    }
}

// ---------------- GEMM: g_h = fp16( dinv[r] * (X @ W) ) -----------------------
// Round-7 inner structure (conflict-free Xs[16][132], float4 LDS + PACK2).
// LAYER==1: input = g_agg1 with BN+PReLU fused on load; BN finalize computed
// per-block in smem from g_sum[0]/g_sumsq[0].
template<int LAYER>
__global__ void __launch_bounds__(256, 2)
gemm_kernel(const float* __restrict__ Xext, const float* __restrict__ W,
            const float* __restrict__ gbn, const float* __restrict__ bebn,
            const float* __restrict__ alpha, float inv_n, int n)
{
    __shared__ float Xs[16][132];   // padded: kills stride-128 bank conflicts
    __shared__ float Ws[16][128];
    __shared__ float s_sc[128], s_sh[128];

    const float* __restrict__ X = (LAYER == 0) ? Xext : g_agg1;

    int tid  = threadIdx.x;
    int row0 = blockIdx.x * 128;
    int tx = tid & 15, ty = tid >> 4;
    float al = (LAYER == 1) ? __ldg(alpha) : 0.f;

    if (LAYER == 1) {                 // per-block BN finalize (cheap, deterministic)
        if (tid < 128) {
            float mu  = g_sum[0][tid] * inv_n;
            float var = g_sumsq[0][tid] * inv_n - mu * mu;
            float rs  = rsqrtf(var + 1e-5f);
            float scl = gbn[tid] * rs;
            s_sc[tid] = scl;
            s_sh[tid] = bebn[tid] - mu * scl;
        }
        __syncthreads();
    }

    unsigned long long acc2[8][4];              // 8 rows x 4 packed col-pairs
    {
        unsigned long long z; PACK2(z, 0.f, 0.f);
#pragma unroll
        for (int i = 0; i < 8; i++)
#pragma unroll
            for (int j = 0; j < 4; j++) acc2[i][j] = z;
    }

    for (int k0 = 0; k0 < D; k0 += 16) {
#pragma unroll
        for (int l = 0; l < 2; l++) {
            int idx = tid + l * 256;            // 512 float4 slots = 128x16 tile
            int r = idx >> 2, c4 = idx & 3;
            int gr = row0 + r;
            float4 v = make_float4(0.f, 0.f, 0.f, 0.f);
            if (gr < n) v = *(const float4*)(X + (size_t)gr * D + k0 + c4 * 4);
            if (LAYER == 1) {
                int c = k0 + c4 * 4;
                float4 s4 = *(const float4*)&s_sc[c];
                float4 h4 = *(const float4*)&s_sh[c];
                v.x = fmaf(s4.x, v.x, h4.x); v.x = v.x > 0.f ? v.x : al * v.x;
                v.y = fmaf(s4.y, v.y, h4.y); v.y = v.y > 0.f ? v.y : al * v.y;
                v.z = fmaf(s4.z, v.z, h4.z); v.z = v.z > 0.f ? v.z : al * v.z;
                v.w = fmaf(s4.w, v.w, h4.w); v.w = v.w > 0.f ? v.w : al * v.w;
            }
            Xs[c4 * 4 + 0][r] = v.x; Xs[c4 * 4 + 1][r] = v.y;
            Xs[c4 * 4 + 2][r] = v.z; Xs[c4 * 4 + 3][r] = v.w;
        }
#pragma unroll
        for (int l = 0; l < 2; l++) {
            int idx = tid + l * 256;
            int r = idx >> 5, c4 = idx & 31;
            *(float4*)&Ws[r][c4 * 4] = *(const float4*)(W + (size_t)(k0 + r) * D + c4 * 4);
        }
        __syncthreads();

#pragma unroll
        for (int kk = 0; kk < 16; kk++) {
            float a[8];
            *(float4*)&a[0] = *(const float4*)&Xs[kk][ty * 8];
            *(float4*)&a[4] = *(const float4*)&Xs[kk][ty * 8 + 4];
            unsigned long long a2[8], b2[4];
#pragma unroll
            for (int i = 0; i < 8; i++) PACK2(a2[i], a[i], a[i]);
#pragma unroll
            for (int j = 0; j < 4; j++)
                b2[j] = *(const unsigned long long*)&Ws[kk][tx * 8 + j * 2];
#pragma unroll
            for (int i = 0; i < 8; i++)
#pragma unroll
                for (int j = 0; j < 4; j++)
                    FMA2(acc2[i][j], a2[i], b2[j], acc2[i][j]);
        }
        __syncthreads();
    }

    // epilogue: scale by dinv, convert to fp16, one 16B store of 8 halves per row
#pragma unroll
    for (int i = 0; i < 8; i++) {
        int r = row0 + ty * 8 + i;
        if (r < n) {
            float dv = g_dinv[r];
            float e[8];
#pragma unroll
            for (int j = 0; j < 4; j++) {
                float lo, hi;
                UNPACK2(lo, hi, acc2[i][j]);
                e[j * 2 + 0] = lo * dv;
                e[j * 2 + 1] = hi * dv;
            }
            __half2 p[4];
#pragma unroll
            for (int j = 0; j < 4; j++)
                p[j] = __floats2half2_rn(e[j * 2], e[j * 2 + 1]);
            *(uint4*)(g_h + (size_t)r * D + tx * 8) = *(uint4*)p;
        }
    }
}

// ---------------- CSR gather: warp per (node, half-row), deep-MLP + idx prefetch ----
template<int LAYER>
__global__ void __launch_bounds__(256)
gather_agg(const float* __restrict__ bias, int n)
{
    int lane = threadIdx.x & 31;
    int warp = (int)((blockIdx.x * blockDim.x + threadIdx.x) >> 5);
    int nwarps = (int)((gridDim.x * blockDim.x) >> 5);
    float* __restrict__ A = (LAYER == 0) ? g_agg1 : g_agg2;
    float* __restrict__ S = g_sum[LAYER];
    float* __restrict__ Q = g_sumsq[LAYER];

    int nitems = 2 * n;
    float2 ss = make_float2(0.f, 0.f);
    float2 qq = make_float2(0.f, 0.f);
    int last_c = 0;

    for (int item = warp; item < nitems; item += nwarps) {
        int node = item >> 1;
        int c = ((item & 1) << 6) + lane * 2;       // column pair
        last_c = c;
        int beg = g_rowptr[node], end = g_rowptr[node + 1];
        const __half* __restrict__ H = g_h + c;

        // self-loop
        float2 acc = __half22float2(*(const __half2*)(H + (size_t)node * D));

        int e = beg;
        // prefetch first index group
        int sv = (e + 8 <= end) ? g_srcs[e + (lane & 7)] : 0;
        while (e + 8 <= end) {
            int sv_cur = sv;
            int en = e + 8;
            if (en + 8 <= end) sv = g_srcs[en + (lane & 7)];   // prefetch next
            int s0 = __shfl_sync(0xffffffffu, sv_cur, 0);
            int s1 = __shfl_sync(0xffffffffu, sv_cur, 1);
            int s2 = __shfl_sync(0xffffffffu, sv_cur, 2);
            int s3 = __shfl_sync(0xffffffffu, sv_cur, 3);
            int s4 = __shfl_sync(0xffffffffu, sv_cur, 4);
            int s5 = __shfl_sync(0xffffffffu, sv_cur, 5);
            int s6 = __shfl_sync(0xffffffffu, sv_cur, 6);
            int s7 = __shfl_sync(0xffffffffu, sv_cur, 7);
            __half2 u0 = *(const __half2*)(H + (size_t)s0 * D);
            __half2 u1 = *(const __half2*)(H + (size_t)s1 * D);
            __half2 u2 = *(const __half2*)(H + (size_t)s2 * D);
            __half2 u3 = *(const __half2*)(H + (size_t)s3 * D);
            __half2 u4 = *(const __half2*)(H + (size_t)s4 * D);
            __half2 u5 = *(const __half2*)(H + (size_t)s5 * D);
            __half2 u6 = *(const __half2*)(H + (size_t)s6 * D);
            __half2 u7 = *(const __half2*)(H + (size_t)s7 * D);
            float2 f0 = __half22float2(u0), f1 = __half22float2(u1);
            float2 f2 = __half22float2(u2), f3 = __half22float2(u3);
            float2 f4 = __half22float2(u4), f5 = __half22float2(u5);
            float2 f6 = __half22float2(u6), f7 = __half22float2(u7);
            acc.x += ((f0.x + f1.x) + (f2.x + f3.x)) + ((f4.x + f5.x) + (f6.x + f7.x));
            acc.y += ((f0.y + f1.y) + (f2.y + f3.y)) + ((f4.y + f5.y) + (f6.y + f7.y));
            e = en;
        }
        for (; e < end; e++) {
            int s = g_srcs[e];
            float2 f = __half22float2(*(const __half2*)(H + (size_t)s * D));
            acc.x += f.x; acc.y += f.y;
        }
        float dv = g_dinv[node];
        float bx = bias[c], by = bias[c + 1];
        float ox = fmaf(dv, acc.x, bx);
        float oy = fmaf(dv, acc.y, by);
        *(float2*)(A + (size_t)node * D + c) = make_float2(ox, oy);
        ss.x += ox; ss.y += oy;
        qq.x = fmaf(ox, ox, qq.x); qq.y = fmaf(oy, oy, qq.y);
    }
    atomicAdd(S + last_c + 0, ss.x); atomicAdd(S + last_c + 1, ss.y);
    atomicAdd(Q + last_c + 0, qq.x); atomicAdd(Q + last_c + 1, qq.y);
}

// ---------------- final apply (BN finalize folded in per-block) ----------------
__global__ void apply_out(const float* __restrict__ g, const float* __restrict__ be,
                          const float* __restrict__ alpha, float inv_n,
                          float* __restrict__ out, int n)
{
    __shared__ float s_sc[128], s_sh[128];
    int t = threadIdx.x;
    if (t < 128) {
        float mu  = g_sum[1][t] * inv_n;
        float var = g_sumsq[1][t] * inv_n - mu * mu;
        float rs  = rsqrtf(var + 1e-5f);
        float scl = g[t] * rs;
        s_sc[t] = scl;
        s_sh[t] = be[t] - mu * scl;
    }
    __syncthreads();

    int i = blockIdx.x * blockDim.x + t;        // one float4 each
    if (i >= n * 32) return;
    int c = (i & 31) * 4;
    float al = __ldg(alpha);
    float4 v  = *(const float4*)(g_agg2 + (size_t)i * 4);
    float4 s4 = *(const float4*)&s_sc[c];
    float4 h4 = *(const float4*)&s_sh[c];
    v.x = fmaf(s4.x, v.x, h4.x); v.x = v.x > 0.f ? v.x : al * v.x;
    v.y = fmaf(s4.y, v.y, h4.y); v.y = v.y > 0.f ? v.y : al * v.y;
    v.z = fmaf(s4.z, v.z, h4.z); v.z = v.z > 0.f ? v.z : al * v.z;
    v.w = fmaf(s4.w, v.w, h4.w); v.w = v.w > 0.f ? v.w : al * v.w;
    *(float4*)(out + (size_t)i * 4) = v;
}

// ---------------- launch ----------------
extern "C" void kernel_launch(void* const* d_in, const int* in_sizes, int n_in,
                              void* d_out, int out_size)
{
    const float* x   = (const float*)d_in[0];
    const void*  ei  = d_in[1];
    const float* W1  = (const float*)d_in[2];
    const float* b1  = (const float*)d_in[3];
    const float* g1  = (const float*)d_in[4];
    const float* be1 = (const float*)d_in[5];
    const float* a1  = (const float*)d_in[6];
    const float* W2  = (const float*)d_in[7];
    const float* b2  = (const float*)d_in[8];
    const float* g2  = (const float*)d_in[9];
    const float* be2 = (const float*)d_in[10];
    const float* a2  = (const float*)d_in[11];

    int ne = in_sizes[1] / 2;        // 2*E elements either way
    int n  = in_sizes[0] / D;
    float inv_n = 1.f / (float)n;

    int nb256  = (n + 255) / 256;
    int eb256  = (ne + 255) / 256;
    int gemm_b = (n + 127) / 128;
    int gat_b  = 1184;               // ~full residency: 148 SMs x 8 blocks
    int out_b  = (n * 32 + 255) / 256;
    int probe_words = (2 * ne < 4096) ? 2 * ne : 4096;
    int nblk1024 = (n + 1023) / 1024;

    init_zero_detect<<<nb256, 256>>>((const int*)ei, probe_words, n);   // 1
    count_deg  <<<eb256, 256>>>(ei, ne, n);                             // 2
    scan_phase1<<<nblk1024, 1024>>>(n);                                 // 3
    scan_phase3<<<(n + 1024) / 1024, 1024>>>(n, nblk1024);              // 4
    fill_buckets<<<eb256, 256>>>(ei, ne, n);                            // 5

    // ---- layer 1 ----  (launch #6 = gemm<0> lands in the ncu -s 5 window)
    gemm_kernel<0><<<gemm_b, 256>>>(x, W1, nullptr, nullptr, a1, 0.f, n);
    gather_agg<0> <<<gat_b, 256>>>(b1, n);                              // 7

    // ---- layer 2 (BN+PReLU of layer 1 fused into GEMM load) ----
    gemm_kernel<1><<<gemm_b, 256>>>(nullptr, W2, g1, be1, a1, inv_n, n);// 8
    gather_agg<1> <<<gat_b, 256>>>(b2, n);                              // 9

    apply_out<<<out_b, 256>>>(g2, be2, a2, inv_n, (float*)d_out, n);    // 10
}

// round 11
// speedup vs baseline: 1.1705x; 1.0811x over previous
#include <cuda_runtime.h>
#include <cuda_fp16.h>

#define NN 50000
#define EE 800000
#define D  128

// ---------------- scratch (static device globals: allowed) ----------------
__device__ __half g_h [(size_t)NN * D];    // UNSCALED messages h = X@W, fp16
__device__ float g_agg1[(size_t)NN * D];   // layer-1 aggregation output (fp32)
__device__ float g_agg2[(size_t)NN * D];   // layer-2 aggregation output (fp32)
__device__ float g_dinv[NN];
__device__ int   g_cnt [NN];               // degree histogram / fill counters
__device__ int   g_rowptr[NN + 1];
__device__ int   g_srcs[EE];               // src ids bucketed by dst
__device__ int   g_tmp [NN];               // intra-block inclusive scan values
__device__ int   g_bsum[64];               // per-block totals
__device__ float g_sum  [2][D];
__device__ float g_sumsq[2][D];
__device__ int   g_is64;                   // 1 if edge_index is really int64

// ---------------- f32x2 packed-FMA helpers (sm_103a) ----------------
#define FMA2(d, a, b, c) \
    asm("fma.rn.f32x2 %0, %1, %2, %3;" : "=l"(d) : "l"(a), "l"(b), "l"(c))
#define PACK2(d, lo, hi) \
    asm("mov.b64 %0, {%1, %2};" : "=l"(d) : "f"(lo), "f"(hi))
#define UNPACK2(lo, hi, v) \
    asm("mov.b64 {%0, %1}, %2;" : "=f"(lo), "=f"(hi) : "l"(v))

__device__ __forceinline__ int edge_at(const void* ei, long long idx, int is64) {
    if (is64) return (int)((const long long*)ei)[idx];
    return ((const int*)ei)[idx];
}

// ---------------- init: zero counters/stats + dtype probe (block 0) ----------------
__global__ void init_zero_detect(const int* __restrict__ words, int nwords, int n) {
    int i = blockIdx.x * blockDim.x + threadIdx.x;
    if (i < n) g_cnt[i] = 0;
    if (i < D) {
        g_sum[0][i] = 0.f; g_sumsq[0][i] = 0.f;
        g_sum[1][i] = 0.f; g_sumsq[1][i] = 0.f;
    }
    if (blockIdx.x == 0) {
        __shared__ int s_nz;
        int t = threadIdx.x;
        if (t == 0) s_nz = 0;
        __syncthreads();
        int nz = 0;
        for (int w = 2 * t + 1; w < nwords; w += 2 * blockDim.x)
            nz |= (words[w] != 0);
        if (nz) atomicOr(&s_nz, 1);
        __syncthreads();
        if (t == 0) g_is64 = s_nz ? 0 : 1;
    }
}

// ---------------- CSR build ----------------
__global__ void count_deg(const void* __restrict__ ei, int ne, int n) {
    int e = blockIdx.x * blockDim.x + threadIdx.x;
    if (e >= ne) return;
    int is64 = g_is64;
    int d = edge_at(ei, (long long)ne + e, is64);       // dst
    if ((unsigned)d < (unsigned)n) atomicAdd(&g_cnt[d], 1);
}

__global__ void scan_phase1(int n) {            // grid = ceil(n/1024), 1024 thr
    __shared__ int sh[1024];
    int t = threadIdx.x;
    int i = blockIdx.x * 1024 + t;
    int v = (i < n) ? g_cnt[i] : 0;
    sh[t] = v;
    __syncthreads();
#pragma unroll
    for (int off = 1; off < 1024; off <<= 1) {
        int u = (t >= off) ? sh[t - off] : 0;
        __syncthreads();
        sh[t] += u;
        __syncthreads();
    }
    if (i < n) g_tmp[i] = sh[t];                // inclusive within block
    if (t == 1023) g_bsum[blockIdx.x] = sh[1023];
}

// phase3 with embedded block-sum scan (phase2 done redundantly per block)
__global__ void scan_phase3(int n, int nblk) {  // 1024 thr
    __shared__ int sbs[64];
    int t = threadIdx.x;
    if (t < 64) sbs[t] = (t < nblk) ? g_bsum[t] : 0;
    __syncthreads();
#pragma unroll
    for (int off = 1; off < 64; off <<= 1) {
        int v = (t < 64 && t >= off) ? sbs[t - off] : 0;
        __syncthreads();
        if (t < 64) sbs[t] += v;
        __syncthreads();
    }
    int i = blockIdx.x * blockDim.x + t;
    if (i > n) return;
    if (i == n) { g_rowptr[n] = sbs[nblk - 1]; return; }
    int blk = i >> 10;
    int c = g_cnt[i];
    int excl = g_tmp[i] - c + (blk ? sbs[blk - 1] : 0);
    g_rowptr[i] = excl;
    g_dinv[i] = rsqrtf((float)(c + 1));         // +1 self-loop
    g_cnt[i] = 0;
}

__global__ void fill_buckets(const void* __restrict__ ei, int ne, int n) {
    int e = blockIdx.x * blockDim.x + threadIdx.x;
    if (e >= ne) return;
    int is64 = g_is64;
    int s = edge_at(ei, e, is64);                        // src
    int d = edge_at(ei, (long long)ne + e, is64);        // dst
    if ((unsigned)d < (unsigned)n && (unsigned)s < (unsigned)n) {
        int p = g_rowptr[d] + atomicAdd(&g_cnt[d], 1);
        g_srcs[p] = s;
    }
}

// ---------------- GEMM: g_h = fp16( X @ W )  (UNSCALED: no dinv dependency) ------
// LAYER==1: input = g_agg1 with BN+PReLU fused on load; BN finalize computed
// per-block in smem from g_sum[0]/g_sumsq[0].
template<int LAYER>
__global__ void __launch_bounds__(256, 2)
gemm_kernel(const float* __restrict__ Xext, const float* __restrict__ W,
            const float* __restrict__ gbn, const float* __restrict__ bebn,
            const float* __restrict__ alpha, float inv_n, int n)
{
    __shared__ float Xs[16][132];   // padded: kills stride-128 bank conflicts
    __shared__ float Ws[16][128];
    __shared__ float s_sc[128], s_sh[128];

    const float* __restrict__ X = (LAYER == 0) ? Xext : g_agg1;

    int tid  = threadIdx.x;
    int row0 = blockIdx.x * 128;
    int tx = tid & 15, ty = tid >> 4;
    float al = (LAYER == 1) ? __ldg(alpha) : 0.f;

    if (LAYER == 1) {                 // per-block BN finalize (cheap, deterministic)
        if (tid < 128) {
            float mu  = g_sum[0][tid] * inv_n;
            float var = g_sumsq[0][tid] * inv_n - mu * mu;
            float rs  = rsqrtf(var + 1e-5f);
            float scl = gbn[tid] * rs;
            s_sc[tid] = scl;
            s_sh[tid] = bebn[tid] - mu * scl;
        }
        __syncthreads();
    }

    unsigned long long acc2[8][4];              // 8 rows x 4 packed col-pairs
    {
        unsigned long long z; PACK2(z, 0.f, 0.f);
#pragma unroll
        for (int i = 0; i < 8; i++)
#pragma unroll
            for (int j = 0; j < 4; j++) acc2[i][j] = z;
    }

    for (int k0 = 0; k0 < D; k0 += 16) {
#pragma unroll
        for (int l = 0; l < 2; l++) {
            int idx = tid + l * 256;            // 512 float4 slots = 128x16 tile
            int r = idx >> 2, c4 = idx & 3;
            int gr = row0 + r;
            float4 v = make_float4(0.f, 0.f, 0.f, 0.f);
            if (gr < n) v = *(const float4*)(X + (size_t)gr * D + k0 + c4 * 4);
            if (LAYER == 1) {
                int c = k0 + c4 * 4;
                float4 s4 = *(const float4*)&s_sc[c];
                float4 h4 = *(const float4*)&s_sh[c];
                v.x = fmaf(s4.x, v.x, h4.x); v.x = v.x > 0.f ? v.x : al * v.x;
                v.y = fmaf(s4.y, v.y, h4.y); v.y = v.y > 0.f ? v.y : al * v.y;
                v.z = fmaf(s4.z, v.z, h4.z); v.z = v.z > 0.f ? v.z : al * v.z;
                v.w = fmaf(s4.w, v.w, h4.w); v.w = v.w > 0.f ? v.w : al * v.w;
            }
            Xs[c4 * 4 + 0][r] = v.x; Xs[c4 * 4 + 1][r] = v.y;
            Xs[c4 * 4 + 2][r] = v.z; Xs[c4 * 4 + 3][r] = v.w;
        }
#pragma unroll
        for (int l = 0; l < 2; l++) {
            int idx = tid + l * 256;
            int r = idx >> 5, c4 = idx & 31;
            *(float4*)&Ws[r][c4 * 4] = *(const float4*)(W + (size_t)(k0 + r) * D + c4 * 4);
        }
        __syncthreads();

#pragma unroll
        for (int kk = 0; kk < 16; kk++) {
            float a[8];
            *(float4*)&a[0] = *(const float4*)&Xs[kk][ty * 8];
            *(float4*)&a[4] = *(const float4*)&Xs[kk][ty * 8 + 4];
            unsigned long long a2[8], b2[4];
#pragma unroll
            for (int i = 0; i < 8; i++) PACK2(a2[i], a[i], a[i]);
#pragma unroll
            for (int j = 0; j < 4; j++)
                b2[j] = *(const unsigned long long*)&Ws[kk][tx * 8 + j * 2];
#pragma unroll
            for (int i = 0; i < 8; i++)
#pragma unroll
                for (int j = 0; j < 4; j++)
                    FMA2(acc2[i][j], a2[i], b2[j], acc2[i][j]);
        }
        __syncthreads();
    }

    // epilogue: convert to fp16 (unscaled), one 16B store of 8 halves per row
#pragma unroll
    for (int i = 0; i < 8; i++) {
        int r = row0 + ty * 8 + i;
        if (r < n) {
            float e[8];
#pragma unroll
            for (int j = 0; j < 4; j++) {
                float lo, hi;
                UNPACK2(lo, hi, acc2[i][j]);
                e[j * 2 + 0] = lo;
                e[j * 2 + 1] = hi;
            }
            __half2 p[4];
#pragma unroll
            for (int j = 0; j < 4; j++)
                p[j] = __floats2half2_rn(e[j * 2], e[j * 2 + 1]);
            *(uint4*)(g_h + (size_t)r * D + tx * 8) = *(uint4*)p;
        }
    }
}

// ---------------- CSR gather: warp per (node, half-row) -----------------------
// Messages unscaled; per-src dinv applied here via FMA (FMA pipe idle anyway).
// out[d] = dinv_d * ( Σ dinv_s·h_s + dinv_d·h_d ) + bias
template<int LAYER>
__global__ void __launch_bounds__(256)
gather_agg(const float* __restrict__ bias, int n)
{
    int lane = threadIdx.x & 31;
    int warp = (int)((blockIdx.x * blockDim.x + threadIdx.x) >> 5);
    int nwarps = (int)((gridDim.x * blockDim.x) >> 5);
    float* __restrict__ A = (LAYER == 0) ? g_agg1 : g_agg2;
    float* __restrict__ S = g_sum[LAYER];
    float* __restrict__ Q = g_sumsq[LAYER];

    int nitems = 2 * n;
    float2 ss = make_float2(0.f, 0.f);
    float2 qq = make_float2(0.f, 0.f);
    int last_c = 0;

    for (int item = warp; item < nitems; item += nwarps) {
        int node = item >> 1;
        int c = ((item & 1) << 6) + lane * 2;       // column pair
        last_c = c;
        int beg = g_rowptr[node], end = g_rowptr[node + 1];
        const __half* __restrict__ H = g_h + c;
        float dv = g_dinv[node];

        // self-loop: dinv_node * h_node
        float2 acc;
        {
            float2 f = __half22float2(*(const __half2*)(H + (size_t)node * D));
            acc = make_float2(f.x * dv, f.y * dv);
        }

        int e = beg;
        // prefetch first index+dinv group
        int sv = (e + 8 <= end) ? g_srcs[e + (lane & 7)] : 0;
        float dvv = (e + 8 <= end) ? g_dinv[sv] : 0.f;
        while (e + 8 <= end) {
            int sv_cur = sv; float dv_cur = dvv;
            int en = e + 8;
            if (en + 8 <= end) {                       // prefetch next group
                sv = g_srcs[en + (lane & 7)];
                dvv = g_dinv[sv];
            }
            int s0 = __shfl_sync(0xffffffffu, sv_cur, 0);
            int s1 = __shfl_sync(0xffffffffu, sv_cur, 1);
            int s2 = __shfl_sync(0xffffffffu, sv_cur, 2);
            int s3 = __shfl_sync(0xffffffffu, sv_cur, 3);
            int s4 = __shfl_sync(0xffffffffu, sv_cur, 4);
            int s5 = __shfl_sync(0xffffffffu, sv_cur, 5);
            int s6 = __shfl_sync(0xffffffffu, sv_cur, 6);
            int s7 = __shfl_sync(0xffffffffu, sv_cur, 7);
            __half2 u0 = *(const __half2*)(H + (size_t)s0 * D);
            __half2 u1 = *(const __half2*)(H + (size_t)s1 * D);
            __half2 u2 = *(const __half2*)(H + (size_t)s2 * D);
            __half2 u3 = *(const __half2*)(H + (size_t)s3 * D);
            __half2 u4 = *(const __half2*)(H + (size_t)s4 * D);
            __half2 u5 = *(const __half2*)(H + (size_t)s5 * D);
            __half2 u6 = *(const __half2*)(H + (size_t)s6 * D);
            __half2 u7 = *(const __half2*)(H + (size_t)s7 * D);
            float d0 = __shfl_sync(0xffffffffu, dv_cur, 0);
            float d1 = __shfl_sync(0xffffffffu, dv_cur, 1);
            float d2 = __shfl_sync(0xffffffffu, dv_cur, 2);
            float d3 = __shfl_sync(0xffffffffu, dv_cur, 3);
            float d4 = __shfl_sync(0xffffffffu, dv_cur, 4);
            float d5 = __shfl_sync(0xffffffffu, dv_cur, 5);
            float d6 = __shfl_sync(0xffffffffu, dv_cur, 6);
            float d7 = __shfl_sync(0xffffffffu, dv_cur, 7);
            float2 f0 = __half22float2(u0), f1 = __half22float2(u1);
            float2 f2 = __half22float2(u2), f3 = __half22float2(u3);
            float2 f4 = __half22float2(u4), f5 = __half22float2(u5);
            float2 f6 = __half22float2(u6), f7 = __half22float2(u7);
            acc.x = fmaf(f0.x, d0, acc.x); acc.y = fmaf(f0.y, d0, acc.y);
            acc.x = fmaf(f1.x, d1, acc.x); acc.y = fmaf(f1.y, d1, acc.y);
            acc.x = fmaf(f2.x, d2, acc.x); acc.y = fmaf(f2.y, d2, acc.y);
            acc.x = fmaf(f3.x, d3, acc.x); acc.y = fmaf(f3.y, d3, acc.y);
            acc.x = fmaf(f4.x, d4, acc.x); acc.y = fmaf(f4.y, d4, acc.y);
            acc.x = fmaf(f5.x, d5, acc.x); acc.y = fmaf(f5.y, d5, acc.y);
            acc.x = fmaf(f6.x, d6, acc.x); acc.y = fmaf(f6.y, d6, acc.y);
            acc.x = fmaf(f7.x, d7, acc.x); acc.y = fmaf(f7.y, d7, acc.y);
            e = en;
        }
        for (; e < end; e++) {
            int s = g_srcs[e];
            float ds = g_dinv[s];
            float2 f = __half22float2(*(const __half2*)(H + (size_t)s * D));
            acc.x = fmaf(f.x, ds, acc.x); acc.y = fmaf(f.y, ds, acc.y);
        }
        float bx = bias[c], by = bias[c + 1];
        float ox = fmaf(dv, acc.x, bx);
        float oy = fmaf(dv, acc.y, by);
        *(float2*)(A + (size_t)node * D + c) = make_float2(ox, oy);
        ss.x += ox; ss.y += oy;
        qq.x = fmaf(ox, ox, qq.x); qq.y = fmaf(oy, oy, qq.y);
    }
    atomicAdd(S + last_c + 0, ss.x); atomicAdd(S + last_c + 1, ss.y);
    atomicAdd(Q + last_c + 0, qq.x); atomicAdd(Q + last_c + 1, qq.y);
}

// ---------------- final apply (BN finalize folded in per-block) ----------------
__global__ void apply_out(const float* __restrict__ g, const float* __restrict__ be,
                          const float* __restrict__ alpha, float inv_n,
                          float* __restrict__ out, int n)
{
    __shared__ float s_sc[128], s_sh[128];
    int t = threadIdx.x;
    if (t < 128) {
        float mu  = g_sum[1][t] * inv_n;
        float var = g_sumsq[1][t] * inv_n - mu * mu;
        float rs  = rsqrtf(var + 1e-5f);
        float scl = g[t] * rs;
        s_sc[t] = scl;
        s_sh[t] = be[t] - mu * scl;
    }
    __syncthreads();

    int i = blockIdx.x * blockDim.x + t;        // one float4 each
    if (i >= n * 32) return;
    int c = (i & 31) * 4;
    float al = __ldg(alpha);
    float4 v  = *(const float4*)(g_agg2 + (size_t)i * 4);
    float4 s4 = *(const float4*)&s_sc[c];
    float4 h4 = *(const float4*)&s_sh[c];
    v.x = fmaf(s4.x, v.x, h4.x); v.x = v.x > 0.f ? v.x : al * v.x;
    v.y = fmaf(s4.y, v.y, h4.y); v.y = v.y > 0.f ? v.y : al * v.y;
    v.z = fmaf(s4.z, v.z, h4.z); v.z = v.z > 0.f ? v.z : al * v.z;
    v.w = fmaf(s4.w, v.w, h4.w); v.w = v.w > 0.f ? v.w : al * v.w;
    *(float4*)(out + (size_t)i * 4) = v;
}

// ---------------- launch ----------------
extern "C" void kernel_launch(void* const* d_in, const int* in_sizes, int n_in,
                              void* d_out, int out_size)
{
    const float* x   = (const float*)d_in[0];
    const void*  ei  = d_in[1];
    const float* W1  = (const float*)d_in[2];
    const float* b1  = (const float*)d_in[3];
    const float* g1  = (const float*)d_in[4];
    const float* be1 = (const float*)d_in[5];
    const float* a1  = (const float*)d_in[6];
    const float* W2  = (const float*)d_in[7];
    const float* b2  = (const float*)d_in[8];
    const float* g2  = (const float*)d_in[9];
    const float* be2 = (const float*)d_in[10];
    const float* a2  = (const float*)d_in[11];

    int ne = in_sizes[1] / 2;        // 2*E elements either way
    int n  = in_sizes[0] / D;
    float inv_n = 1.f / (float)n;

    int nb256  = (n + 255) / 256;
    int eb256  = (ne + 255) / 256;
    int gemm_b = (n + 127) / 128;
    int gat_b  = 1184;               // ~full residency: 148 SMs x 8 blocks
    int out_b  = (n * 32 + 255) / 256;
    int probe_words = (2 * ne < 4096) ? 2 * ne : 4096;
    int nblk1024 = (n + 1023) / 1024;

    // side stream + events (host-side resources, created once; no device alloc)
    static cudaStream_t s_side = nullptr;
    static cudaEvent_t  s_fork = nullptr, s_join = nullptr;
    if (s_side == nullptr) {
        cudaStreamCreateWithFlags(&s_side, cudaStreamNonBlocking);
        cudaEventCreateWithFlags(&s_fork, cudaEventDisableTiming);
        cudaEventCreateWithFlags(&s_join, cudaEventDisableTiming);
    }

    // ---- fork: gemm<0> (depends only on x, W1) runs parallel to CSR build ----
    cudaEventRecord(s_fork, 0);
    cudaStreamWaitEvent(s_side, s_fork, 0);
    gemm_kernel<0><<<gemm_b, 256, 0, s_side>>>(x, W1, nullptr, nullptr, a1, 0.f, n);
    cudaEventRecord(s_join, s_side);

    // ---- main stream: CSR build ----
    init_zero_detect<<<nb256, 256>>>((const int*)ei, probe_words, n);
    count_deg  <<<eb256, 256>>>(ei, ne, n);
    scan_phase1<<<nblk1024, 1024>>>(n);
    scan_phase3<<<(n + 1024) / 1024, 1024>>>(n, nblk1024);
    fill_buckets<<<eb256, 256>>>(ei, ne, n);

    // ---- join, then layer-1 gather ----
    cudaStreamWaitEvent(0, s_join, 0);
    gather_agg<0><<<gat_b, 256>>>(b1, n);

    // ---- layer 2 (BN+PReLU of layer 1 fused into GEMM load) ----
    gemm_kernel<1><<<gemm_b, 256>>>(nullptr, W2, g1, be1, a1, inv_n, n);
    gather_agg<1><<<gat_b, 256>>>(b2, n);

    apply_out<<<out_b, 256>>>(g2, be2, a2, inv_n, (float*)d_out, n);
}

// round 12
// speedup vs baseline: 1.4158x; 1.2096x over previous
#include <cuda_runtime.h>
#include <cuda_fp16.h>

#define NN 50000
#define EE 800000
#define D  128
#define PITCH 136   // halves per smem row; 272B = 16*17 -> ldmatrix conflict-free

// ---------------- scratch (static device globals: allowed) ----------------
__device__ __half g_h [(size_t)NN * D];    // UNSCALED messages h = X@W, fp16
__device__ float g_agg1[(size_t)NN * D];   // layer-1 aggregation output (fp32)
__device__ float g_agg2[(size_t)NN * D];   // layer-2 aggregation output (fp32)
__device__ float g_dinv[NN];
__device__ int   g_cnt [NN];               // degree histogram / fill counters
__device__ int   g_rowptr[NN + 1];
__device__ int   g_srcs[EE];               // src ids bucketed by dst
__device__ int   g_tmp [NN];               // intra-block inclusive scan values
__device__ int   g_bsum[64];               // per-block totals
__device__ float g_sum  [2][D];
__device__ float g_sumsq[2][D];
__device__ int   g_is64;                   // 1 if edge_index is really int64

__device__ __forceinline__ int edge_at(const void* ei, long long idx, int is64) {
    if (is64) return (int)((const long long*)ei)[idx];
    return ((const int*)ei)[idx];
}

// ---------------- init: zero counters/stats + dtype probe (block 0) ----------------
__global__ void init_zero_detect(const int* __restrict__ words, int nwords, int n) {
    int i = blockIdx.x * blockDim.x + threadIdx.x;
    if (i < n) g_cnt[i] = 0;
    if (i < D) {
        g_sum[0][i] = 0.f; g_sumsq[0][i] = 0.f;
        g_sum[1][i] = 0.f; g_sumsq[1][i] = 0.f;
    }
    if (blockIdx.x == 0) {
        __shared__ int s_nz;
        int t = threadIdx.x;
        if (t == 0) s_nz = 0;
        __syncthreads();
        int nz = 0;
        for (int w = 2 * t + 1; w < nwords; w += 2 * blockDim.x)
            nz |= (words[w] != 0);
        if (nz) atomicOr(&s_nz, 1);
        __syncthreads();
        if (t == 0) g_is64 = s_nz ? 0 : 1;
    }
}

// ---------------- CSR build ----------------
__global__ void count_deg(const void* __restrict__ ei, int ne, int n) {
    int e = blockIdx.x * blockDim.x + threadIdx.x;
    if (e >= ne) return;
    int is64 = g_is64;
    int d = edge_at(ei, (long long)ne + e, is64);       // dst
    if ((unsigned)d < (unsigned)n) atomicAdd(&g_cnt[d], 1);
}

__global__ void scan_phase1(int n) {            // grid = ceil(n/1024), 1024 thr
    __shared__ int sh[1024];
    int t = threadIdx.x;
    int i = blockIdx.x * 1024 + t;
    int v = (i < n) ? g_cnt[i] : 0;
    sh[t] = v;
    __syncthreads();
#pragma unroll
    for (int off = 1; off < 1024; off <<= 1) {
        int u = (t >= off) ? sh[t - off] : 0;
        __syncthreads();
        sh[t] += u;
        __syncthreads();
    }
    if (i < n) g_tmp[i] = sh[t];                // inclusive within block
    if (t == 1023) g_bsum[blockIdx.x] = sh[1023];
}

// phase3 with embedded block-sum scan (phase2 done redundantly per block)
__global__ void scan_phase3(int n, int nblk) {  // 1024 thr
    __shared__ int sbs[64];
    int t = threadIdx.x;
    if (t < 64) sbs[t] = (t < nblk) ? g_bsum[t] : 0;
    __syncthreads();
#pragma unroll
    for (int off = 1; off < 64; off <<= 1) {
        int v = (t < 64 && t >= off) ? sbs[t - off] : 0;
        __syncthreads();
        if (t < 64) sbs[t] += v;
        __syncthreads();
    }
    int i = blockIdx.x * blockDim.x + t;
    if (i > n) return;
    if (i == n) { g_rowptr[n] = sbs[nblk - 1]; return; }
    int blk = i >> 10;
    int c = g_cnt[i];
    int excl = g_tmp[i] - c + (blk ? sbs[blk - 1] : 0);
    g_rowptr[i] = excl;
    g_dinv[i] = rsqrtf((float)(c + 1));         // +1 self-loop
    g_cnt[i] = 0;
}

__global__ void fill_buckets(const void* __restrict__ ei, int ne, int n) {
    int e = blockIdx.x * blockDim.x + threadIdx.x;
    if (e >= ne) return;
    int is64 = g_is64;
    int s = edge_at(ei, e, is64);                        // src
    int d = edge_at(ei, (long long)ne + e, is64);        // dst
    if ((unsigned)d < (unsigned)n && (unsigned)s < (unsigned)n) {
        int p = g_rowptr[d] + atomicAdd(&g_cnt[d], 1);
        g_srcs[p] = s;
    }
}

// ---------------- tensor-core GEMM: g_h = fp16( X @ W ), fp32 accumulate --------
// mma.sync.m16n8k16 row.col, fp16 operands. Block tile 128x128, full K=128 in
// smem (pitch 136 halves -> conflict-free ldmatrix). 8 warps in 4(m) x 2(n).
// LAYER==1: input = g_agg1 with BN+PReLU fused on load (fp32 math, then fp16).
template<int LAYER>
__global__ void __launch_bounds__(256, 2)
gemm_kernel(const float* __restrict__ Xext, const float* __restrict__ W,
            const float* __restrict__ gbn, const float* __restrict__ bebn,
            const float* __restrict__ alpha, float inv_n, int n)
{
    extern __shared__ __half smem_dyn[];
    __half* As = smem_dyn;                  // [128][PITCH]
    __half* Bs = smem_dyn + 128 * PITCH;    // [128][PITCH]
    __shared__ float s_sc[128], s_sh[128];

    const float* __restrict__ X = (LAYER == 0) ? Xext : g_agg1;

    int tid  = threadIdx.x;
    int row0 = blockIdx.x * 128;
    float al = (LAYER == 1) ? __ldg(alpha) : 0.f;

    if (LAYER == 1) {                 // per-block BN finalize (cheap, deterministic)
        if (tid < 128) {
            float mu  = g_sum[0][tid] * inv_n;
            float var = g_sumsq[0][tid] * inv_n - mu * mu;
            float rs  = rsqrtf(var + 1e-5f);
            float scl = gbn[tid] * rs;
            s_sc[tid] = scl;
            s_sh[tid] = bebn[tid] - mu * scl;
        }
        __syncthreads();
    }

    // ---- load A (X rows, fp32 -> fp16, optional BN+PReLU) and B (W) ----
#pragma unroll
    for (int t = 0; t < 16; t++) {          // 4096 float4s of A
        int idx = tid + t * 256;
        int r = idx >> 5, c4 = idx & 31;    // row 0..127, col group 0..31
        int col = c4 * 4;
        int gr = row0 + r;
        float4 v = make_float4(0.f, 0.f, 0.f, 0.f);
        if (gr < n) v = *(const float4*)(X + (size_t)gr * D + col);
        if (LAYER == 1) {
            float4 s4 = *(const float4*)&s_sc[col];
            float4 h4 = *(const float4*)&s_sh[col];
            v.x = fmaf(s4.x, v.x, h4.x); v.x = v.x > 0.f ? v.x : al * v.x;
            v.y = fmaf(s4.y, v.y, h4.y); v.y = v.y > 0.f ? v.y : al * v.y;
            v.z = fmaf(s4.z, v.z, h4.z); v.z = v.z > 0.f ? v.z : al * v.z;
            v.w = fmaf(s4.w, v.w, h4.w); v.w = v.w > 0.f ? v.w : al * v.w;
        }
        __half2 h01 = __floats2half2_rn(v.x, v.y);
        __half2 h23 = __floats2half2_rn(v.z, v.w);
        *(__half2*)(As + r * PITCH + col)     = h01;
        *(__half2*)(As + r * PITCH + col + 2) = h23;
    }
#pragma unroll
    for (int t = 0; t < 16; t++) {          // 4096 float4s of B (W is 128x128)
        int idx = tid + t * 256;
        int r = idx >> 5, c4 = idx & 31;
        int col = c4 * 4;
        float4 v = *(const float4*)(W + (size_t)r * D + col);
        __half2 h01 = __floats2half2_rn(v.x, v.y);
        __half2 h23 = __floats2half2_rn(v.z, v.w);
        *(__half2*)(Bs + r * PITCH + col)     = h01;
        *(__half2*)(Bs + r * PITCH + col + 2) = h23;
    }
    __syncthreads();

    // ---- mma compute ----
    int warp = tid >> 5, lane = tid & 31;
    int wm = warp & 3, wn = warp >> 2;      // 4 x 2 warp grid
    int m_base = wm * 32, n_base = wn * 64;
    int g = lane >> 3, r8 = lane & 7;
    int g_lo = g & 1, g_hi = g >> 1;        // tile-row / tile-col selectors

    float acc[2][8][4];
#pragma unroll
    for (int mt = 0; mt < 2; mt++)
#pragma unroll
        for (int nt = 0; nt < 8; nt++)
#pragma unroll
            for (int q = 0; q < 4; q++) acc[mt][nt][q] = 0.f;

    // per-lane base addresses (halves)
    // A group: row = m_base + mt*16 + g_lo*8 + r8 ; col = k*16 + g_hi*8
    // B group: row = k*16 + g_lo*8 + r8 ; col = n_base + nt2*16 + g_hi*8
    unsigned a_base0 = (unsigned)__cvta_generic_to_shared(
        As + (m_base + g_lo * 8 + r8) * PITCH + g_hi * 8);
    unsigned b_base = (unsigned)__cvta_generic_to_shared(
        Bs + (g_lo * 8 + r8) * PITCH + n_base + g_hi * 8);

#pragma unroll
    for (int k = 0; k < 8; k++) {
        unsigned a[2][4];
#pragma unroll
        for (int mt = 0; mt < 2; mt++) {
            unsigned addr = a_base0 + (unsigned)((mt * 16 * PITCH + k * 16) * 2);
            asm volatile("ldmatrix.sync.aligned.m8n8.x4.shared.b16 {%0,%1,%2,%3}, [%4];"
                         : "=r"(a[mt][0]), "=r"(a[mt][1]), "=r"(a[mt][2]), "=r"(a[mt][3])
                         : "r"(addr));
        }
#pragma unroll
        for (int nt2 = 0; nt2 < 4; nt2++) {   // each covers n16 = two n8 frags
            unsigned b0, b1, b2, b3;
            unsigned addr = b_base + (unsigned)((k * 16 * PITCH + nt2 * 16) * 2);
            asm volatile("ldmatrix.sync.aligned.m8n8.x4.trans.shared.b16 {%0,%1,%2,%3}, [%4];"
                         : "=r"(b0), "=r"(b1), "=r"(b2), "=r"(b3)
                         : "r"(addr));
#pragma unroll
            for (int mt = 0; mt < 2; mt++) {
                asm volatile(
                    "mma.sync.aligned.m16n8k16.row.col.f32.f16.f16.f32 "
                    "{%0,%1,%2,%3}, {%4,%5,%6,%7}, {%8,%9}, {%0,%1,%2,%3};"
                    : "+f"(acc[mt][nt2 * 2][0]), "+f"(acc[mt][nt2 * 2][1]),
                      "+f"(acc[mt][nt2 * 2][2]), "+f"(acc[mt][nt2 * 2][3])
                    : "r"(a[mt][0]), "r"(a[mt][1]), "r"(a[mt][2]), "r"(a[mt][3]),
                      "r"(b0), "r"(b1));
                asm volatile(
                    "mma.sync.aligned.m16n8k16.row.col.f32.f16.f16.f32 "
                    "{%0,%1,%2,%3}, {%4,%5,%6,%7}, {%8,%9}, {%0,%1,%2,%3};"
                    : "+f"(acc[mt][nt2 * 2 + 1][0]), "+f"(acc[mt][nt2 * 2 + 1][1]),
                      "+f"(acc[mt][nt2 * 2 + 1][2]), "+f"(acc[mt][nt2 * 2 + 1][3])
                    : "r"(a[mt][0]), "r"(a[mt][1]), "r"(a[mt][2]), "r"(a[mt][3]),
                      "r"(b2), "r"(b3));
            }
        }
    }

    // ---- epilogue: fp16 half2 stores ----
    int erow = lane >> 2, ecol = (lane & 3) * 2;
#pragma unroll
    for (int mt = 0; mt < 2; mt++) {
#pragma unroll
        for (int nt = 0; nt < 8; nt++) {
            int gc = n_base + nt * 8 + ecol;
            int r_lo = row0 + m_base + mt * 16 + erow;
            if (r_lo < n)
                *(__half2*)(g_h + (size_t)r_lo * D + gc) =
                    __floats2half2_rn(acc[mt][nt][0], acc[mt][nt][1]);
            int r_hi = r_lo + 8;
            if (r_hi < n)
                *(__half2*)(g_h + (size_t)r_hi * D + gc) =
                    __floats2half2_rn(acc[mt][nt][2], acc[mt][nt][3]);
        }
    }
}

// ---------------- CSR gather: warp per (node, half-row) -----------------------
// Messages unscaled; per-src dinv applied here via FMA.
// out[d] = dinv_d * ( Σ dinv_s·h_s + dinv_d·h_d ) + bias
template<int LAYER>
__global__ void __launch_bounds__(256)
gather_agg(const float* __restrict__ bias, int n)
{
    int lane = threadIdx.x & 31;
    int warp = (int)((blockIdx.x * blockDim.x + threadIdx.x) >> 5);
    int nwarps = (int)((gridDim.x * blockDim.x) >> 5);
    float* __restrict__ A = (LAYER == 0) ? g_agg1 : g_agg2;
    float* __restrict__ S = g_sum[LAYER];
    float* __restrict__ Q = g_sumsq[LAYER];

    int nitems = 2 * n;
    float2 ss = make_float2(0.f, 0.f);
    float2 qq = make_float2(0.f, 0.f);
    int last_c = 0;

    for (int item = warp; item < nitems; item += nwarps) {
        int node = item >> 1;
        int c = ((item & 1) << 6) + lane * 2;       // column pair
        last_c = c;
        int beg = g_rowptr[node], end = g_rowptr[node + 1];
        const __half* __restrict__ H = g_h + c;
        float dv = g_dinv[node];

        float2 acc;
        {
            float2 f = __half22float2(*(const __half2*)(H + (size_t)node * D));
            acc = make_float2(f.x * dv, f.y * dv);
        }

        int e = beg;
        int sv = (e + 8 <= end) ? g_srcs[e + (lane & 7)] : 0;
        float dvv = (e + 8 <= end) ? g_dinv[sv] : 0.f;
        while (e + 8 <= end) {
            int sv_cur = sv; float dv_cur = dvv;
            int en = e + 8;
            if (en + 8 <= end) {
                sv = g_srcs[en + (lane & 7)];
                dvv = g_dinv[sv];
            }
            int s0 = __shfl_sync(0xffffffffu, sv_cur, 0);
            int s1 = __shfl_sync(0xffffffffu, sv_cur, 1);
            int s2 = __shfl_sync(0xffffffffu, sv_cur, 2);
            int s3 = __shfl_sync(0xffffffffu, sv_cur, 3);
            int s4 = __shfl_sync(0xffffffffu, sv_cur, 4);
            int s5 = __shfl_sync(0xffffffffu, sv_cur, 5);
            int s6 = __shfl_sync(0xffffffffu, sv_cur, 6);
            int s7 = __shfl_sync(0xffffffffu, sv_cur, 7);
            __half2 u0 = *(const __half2*)(H + (size_t)s0 * D);
            __half2 u1 = *(const __half2*)(H + (size_t)s1 * D);
            __half2 u2 = *(const __half2*)(H + (size_t)s2 * D);
            __half2 u3 = *(const __half2*)(H + (size_t)s3 * D);
            __half2 u4 = *(const __half2*)(H + (size_t)s4 * D);
            __half2 u5 = *(const __half2*)(H + (size_t)s5 * D);
            __half2 u6 = *(const __half2*)(H + (size_t)s6 * D);
            __half2 u7 = *(const __half2*)(H + (size_t)s7 * D);
            float d0 = __shfl_sync(0xffffffffu, dv_cur, 0);
            float d1 = __shfl_sync(0xffffffffu, dv_cur, 1);
            float d2 = __shfl_sync(0xffffffffu, dv_cur, 2);
            float d3 = __shfl_sync(0xffffffffu, dv_cur, 3);
            float d4 = __shfl_sync(0xffffffffu, dv_cur, 4);
            float d5 = __shfl_sync(0xffffffffu, dv_cur, 5);
            float d6 = __shfl_sync(0xffffffffu, dv_cur, 6);
            float d7 = __shfl_sync(0xffffffffu, dv_cur, 7);
            float2 f0 = __half22float2(u0), f1 = __half22float2(u1);
            float2 f2 = __half22float2(u2), f3 = __half22float2(u3);
            float2 f4 = __half22float2(u4), f5 = __half22float2(u5);
            float2 f6 = __half22float2(u6), f7 = __half22float2(u7);
            acc.x = fmaf(f0.x, d0, acc.x); acc.y = fmaf(f0.y, d0, acc.y);
            acc.x = fmaf(f1.x, d1, acc.x); acc.y = fmaf(f1.y, d1, acc.y);
            acc.x = fmaf(f2.x, d2, acc.x); acc.y = fmaf(f2.y, d2, acc.y);
            acc.x = fmaf(f3.x, d3, acc.x); acc.y = fmaf(f3.y, d3, acc.y);
            acc.x = fmaf(f4.x, d4, acc.x); acc.y = fmaf(f4.y, d4, acc.y);
            acc.x = fmaf(f5.x, d5, acc.x); acc.y = fmaf(f5.y, d5, acc.y);
            acc.x = fmaf(f6.x, d6, acc.x); acc.y = fmaf(f6.y, d6, acc.y);
            acc.x = fmaf(f7.x, d7, acc.x); acc.y = fmaf(f7.y, d7, acc.y);
            e = en;
        }
        for (; e < end; e++) {
            int s = g_srcs[e];
            float ds = g_dinv[s];
            float2 f = __half22float2(*(const __half2*)(H + (size_t)s * D));
            acc.x = fmaf(f.x, ds, acc.x); acc.y = fmaf(f.y, ds, acc.y);
        }
        float bx = bias[c], by = bias[c + 1];
        float ox = fmaf(dv, acc.x, bx);
        float oy = fmaf(dv, acc.y, by);
        *(float2*)(A + (size_t)node * D + c) = make_float2(ox, oy);
        ss.x += ox; ss.y += oy;
        qq.x = fmaf(ox, ox, qq.x); qq.y = fmaf(oy, oy, qq.y);
    }
    atomicAdd(S + last_c + 0, ss.x); atomicAdd(S + last_c + 1, ss.y);
    atomicAdd(Q + last_c + 0, qq.x); atomicAdd(Q + last_c + 1, qq.y);
}

// ---------------- final apply (BN finalize folded in per-block) ----------------
__global__ void apply_out(const float* __restrict__ g, const float* __restrict__ be,
                          const float* __restrict__ alpha, float inv_n,
                          float* __restrict__ out, int n)
{
    __shared__ float s_sc[128], s_sh[128];
    int t = threadIdx.x;
    if (t < 128) {
        float mu  = g_sum[1][t] * inv_n;
        float var = g_sumsq[1][t] * inv_n - mu * mu;
        float rs  = rsqrtf(var + 1e-5f);
        float scl = g[t] * rs;
        s_sc[t] = scl;
        s_sh[t] = be[t] - mu * scl;
    }
    __syncthreads();

    int i = blockIdx.x * blockDim.x + t;        // one float4 each
    if (i >= n * 32) return;
    int c = (i & 31) * 4;
    float al = __ldg(alpha);
    float4 v  = *(const float4*)(g_agg2 + (size_t)i * 4);
    float4 s4 = *(const float4*)&s_sc[c];
    float4 h4 = *(const float4*)&s_sh[c];
    v.x = fmaf(s4.x, v.x, h4.x); v.x = v.x > 0.f ? v.x : al * v.x;
    v.y = fmaf(s4.y, v.y, h4.y); v.y = v.y > 0.f ? v.y : al * v.y;
    v.z = fmaf(s4.z, v.z, h4.z); v.z = v.z > 0.f ? v.z : al * v.z;
    v.w = fmaf(s4.w, v.w, h4.w); v.w = v.w > 0.f ? v.w : al * v.w;
    *(float4*)(out + (size_t)i * 4) = v;
}

// ---------------- launch ----------------
extern "C" void kernel_launch(void* const* d_in, const int* in_sizes, int n_in,
                              void* d_out, int out_size)
{
    const float* x   = (const float*)d_in[0];
    const void*  ei  = d_in[1];
    const float* W1  = (const float*)d_in[2];
    const float* b1  = (const float*)d_in[3];
    const float* g1  = (const float*)d_in[4];
    const float* be1 = (const float*)d_in[5];
    const float* a1  = (const float*)d_in[6];
    const float* W2  = (const float*)d_in[7];
    const float* b2  = (const float*)d_in[8];
    const float* g2  = (const float*)d_in[9];
    const float* be2 = (const float*)d_in[10];
    const float* a2  = (const float*)d_in[11];

    int ne = in_sizes[1] / 2;        // 2*E elements either way
    int n  = in_sizes[0] / D;
    float inv_n = 1.f / (float)n;

    int nb256  = (n + 255) / 256;
    int eb256  = (ne + 255) / 256;
    int gemm_b = (n + 127) / 128;
    int gat_b  = 1184;               // ~full residency: 148 SMs x 8 blocks
    int out_b  = (n * 32 + 255) / 256;
    int probe_words = (2 * ne < 4096) ? 2 * ne : 4096;
    int nblk1024 = (n + 1023) / 1024;
    size_t gemm_smem = (size_t)2 * 128 * PITCH * sizeof(__half);   // 69632 B

    // one-time host-side setup (no device alloc)
    static cudaStream_t s_side = nullptr;
    static cudaEvent_t  s_fork = nullptr, s_join = nullptr;
    if (s_side == nullptr) {
        cudaStreamCreateWithFlags(&s_side, cudaStreamNonBlocking);
        cudaEventCreateWithFlags(&s_fork, cudaEventDisableTiming);
        cudaEventCreateWithFlags(&s_join, cudaEventDisableTiming);
        cudaFuncSetAttribute(gemm_kernel<0>,
                             cudaFuncAttributeMaxDynamicSharedMemorySize, (int)gemm_smem);
        cudaFuncSetAttribute(gemm_kernel<1>,
                             cudaFuncAttributeMaxDynamicSharedMemorySize, (int)gemm_smem);
    }

    // ---- fork: gemm<0> (depends only on x, W1) runs parallel to CSR build ----
    cudaEventRecord(s_fork, 0);
    cudaStreamWaitEvent(s_side, s_fork, 0);
    gemm_kernel<0><<<gemm_b, 256, gemm_smem, s_side>>>(x, W1, nullptr, nullptr, a1, 0.f, n);
    cudaEventRecord(s_join, s_side);

    // ---- main stream: CSR build ----
    init_zero_detect<<<nb256, 256>>>((const int*)ei, probe_words, n);
    count_deg  <<<eb256, 256>>>(ei, ne, n);
    scan_phase1<<<nblk1024, 1024>>>(n);
    scan_phase3<<<(n + 1024) / 1024, 1024>>>(n, nblk1024);
    fill_buckets<<<eb256, 256>>>(ei, ne, n);

    // ---- join, then layer-1 gather ----
    cudaStreamWaitEvent(0, s_join, 0);
    gather_agg<0><<<gat_b, 256>>>(b1, n);

    // ---- layer 2 (BN+PReLU of layer 1 fused into GEMM load) ----
    gemm_kernel<1><<<gemm_b, 256, gemm_smem>>>(nullptr, W2, g1, be1, a1, inv_n, n);
    gather_agg<1><<<gat_b, 256>>>(b2, n);

    apply_out<<<out_b, 256>>>(g2, be2, a2, inv_n, (float*)d_out, n);
}